// round 13
// baseline (speedup 1.0000x reference)
#include <cuda_runtime.h>
#include <cuda_fp16.h>
#include <math.h>
#include <stdint.h>

// ---------------------------------------------------------------- constants
#define T_TOK 8192
#define Dm    512
#define Fm    2048
#define Em    64
#define Hh    4
#define NC    256
#define CAP   1024
#define NSLOT (T_TOK * 2)

// routing fp32 GEMM tiling
#define BM 128
#define BN 128
#define BK 8

// static fallback FFN kernel (R12-proven): CTA 128x256, KCH=16
#define KCH   16
#define SPAD  24
#define BNP2  264

// dynamic-smem FFN kernel: CTA 128x128, KCH=32, frag double-buffered
#define DKCH  32
#define DSPAD 40     // A row stride (fp16): 32 k + 8 pad  (ldsm conflict-free)
#define DBNP  136    // B row stride (fp16): 128 n + 8 pad
#define A_BYTES (128 * DSPAD * 2)            // 10240
#define B_BYTES (DKCH * DBNP * 2)            // 8704
#define OFF_AH(b) ((b) * 2 * A_BYTES)
#define OFF_AL(b) ((b) * 2 * A_BYTES + A_BYTES)
#define OFF_BH(b) (4 * A_BYTES + (b) * B_BYTES)
#define DSMEM (4 * A_BYTES + 2 * B_BYTES)    // 58368

// ---------------------------------------------------------------- scratch
__device__ __align__(256) float g_logits[(size_t)T_TOK * NC];
__device__ __align__(256) int   g_count[Em];
__device__ __align__(256) int   g_toklist[Em * CAP];
__device__ __align__(256) float g_hbuf[(size_t)NSLOT * Fm];
__device__ __align__(256) float g_ybuf[(size_t)NSLOT * Dm];

// ---------------------------------------------------------------- helpers
__device__ __forceinline__ float gelu_exact(float v) {
    return 0.5f * v * (1.0f + erff(v * 0.7071067811865475f));
}
__device__ __forceinline__ uint32_t pack_h(__half a, __half b) {
    return (uint32_t)__half_as_ushort(a) | ((uint32_t)__half_as_ushort(b) << 16);
}
__device__ __forceinline__ void split4h(float4 v, uint2& h, uint2& l) {
    float f[4] = {v.x, v.y, v.z, v.w};
    __half hh[4], ll[4];
#pragma unroll
    for (int i = 0; i < 4; i++) {
        hh[i] = __float2half_rn(f[i]);
        ll[i] = __float2half_rn(f[i] - __half2float(hh[i]));
    }
    h = make_uint2(pack_h(hh[0], hh[1]), pack_h(hh[2], hh[3]));
    l = make_uint2(pack_h(ll[0], ll[1]), pack_h(ll[2], ll[3]));
}
__device__ __forceinline__ uint2 hi4h(float4 v) {
    return make_uint2(pack_h(__float2half_rn(v.x), __float2half_rn(v.y)),
                      pack_h(__float2half_rn(v.z), __float2half_rn(v.w)));
}
__device__ __forceinline__ void mma_f16(float& d0, float& d1, float& d2, float& d3,
                                        uint32_t a0, uint32_t a1, uint32_t a2, uint32_t a3,
                                        uint32_t b0, uint32_t b1) {
    asm volatile(
        "mma.sync.aligned.m16n8k16.row.col.f32.f16.f16.f32 "
        "{%0,%1,%2,%3},{%4,%5,%6,%7},{%8,%9},{%0,%1,%2,%3};"
        : "+f"(d0), "+f"(d1), "+f"(d2), "+f"(d3)
        : "r"(a0), "r"(a1), "r"(a2), "r"(a3), "r"(b0), "r"(b1));
}
__device__ __forceinline__ void ldsm_x4(uint32_t& r0, uint32_t& r1, uint32_t& r2, uint32_t& r3,
                                        uint32_t addr) {
    asm volatile("ldmatrix.sync.aligned.m8n8.x4.shared.b16 {%0,%1,%2,%3}, [%4];"
                 : "=r"(r0), "=r"(r1), "=r"(r2), "=r"(r3) : "r"(addr));
}
__device__ __forceinline__ void ldsm_x4_t(uint32_t& r0, uint32_t& r1, uint32_t& r2, uint32_t& r3,
                                          uint32_t addr) {
    asm volatile("ldmatrix.sync.aligned.m8n8.x4.trans.shared.b16 {%0,%1,%2,%3}, [%4];"
                 : "=r"(r0), "=r"(r1), "=r"(r2), "=r"(r3) : "r"(addr));
}

// ---------------------------------------------------------------- K0: misc
__global__ void zc_kernel() {
    if (threadIdx.x < Em) g_count[threadIdx.x] = 0;
}

// ---------------------------------------------------------------- routing (proven, fp32-exact)
__global__ __launch_bounds__(256, 2)
void route_gemm(const float* __restrict__ x, const float* __restrict__ hp) {
    __shared__ float As[BK][BM + 4];
    __shared__ float Bs[BK][BN];
    const int tid = threadIdx.x;
    const int bm = blockIdx.y * BM;
    const int bn = blockIdx.x * BN;
    const int arow = tid >> 1, akq = (tid & 1) << 2;
    const int bkr = tid >> 5, bnq = (tid & 31) << 2;
    const int tx = tid & 15, ty = tid >> 4;

    const int c = bn + bnq;
    const float* bsrc = hp + (c >> 6) * (Dm * Em) + bkr * Em + (c & 63);
    const float* asrc = x + (size_t)(bm + arow) * Dm + akq;

    float acc[8][8];
#pragma unroll
    for (int i = 0; i < 8; i++)
#pragma unroll
        for (int j = 0; j < 8; j++) acc[i][j] = 0.0f;

    for (int k0 = 0; k0 < Dm; k0 += BK) {
        float4 av = *(const float4*)(asrc + k0);
        float4 bv = *(const float4*)(bsrc + (size_t)k0 * Em);
        As[akq + 0][arow] = av.x;
        As[akq + 1][arow] = av.y;
        As[akq + 2][arow] = av.z;
        As[akq + 3][arow] = av.w;
        *(float4*)&Bs[bkr][bnq] = bv;
        __syncthreads();
        float ar[8], br[8];
#pragma unroll
        for (int k = 0; k < BK; k++) {
            *(float4*)&ar[0] = *(const float4*)&As[k][ty * 4];
            *(float4*)&ar[4] = *(const float4*)&As[k][64 + ty * 4];
            *(float4*)&br[0] = *(const float4*)&Bs[k][tx * 4];
            *(float4*)&br[4] = *(const float4*)&Bs[k][64 + tx * 4];
#pragma unroll
            for (int i = 0; i < 8; i++)
#pragma unroll
                for (int j = 0; j < 8; j++)
                    acc[i][j] = fmaf(ar[i], br[j], acc[i][j]);
        }
        __syncthreads();
    }
#pragma unroll
    for (int i = 0; i < 8; i++) {
        int m = bm + ((i < 4) ? (ty * 4 + i) : (64 + ty * 4 + i - 4));
        float* dst = g_logits + (size_t)m * NC + bn;
        *(float4*)(dst + tx * 4)      = make_float4(acc[i][0], acc[i][1], acc[i][2], acc[i][3]);
        *(float4*)(dst + 64 + tx * 4) = make_float4(acc[i][4], acc[i][5], acc[i][6], acc[i][7]);
    }
}

// fused top-2 routing + dispatch
__global__ void route_top2_dispatch() {
    int t = (blockIdx.x * blockDim.x + threadIdx.x) >> 5;
    int lane = threadIdx.x & 31;
    if (t >= T_TOK) return;
    const float* lg = g_logits + (size_t)t * NC;
    float sc[Hh]; int cd[Hh];
#pragma unroll
    for (int h = 0; h < Hh; h++) {
        float v0 = lg[h * 64 + lane];
        float v1 = lg[h * 64 + 32 + lane];
        float v = v0; int idx = lane;
        if (v1 > v) { v = v1; idx = lane + 32; }
#pragma unroll
        for (int off = 16; off > 0; off >>= 1) {
            float ov = __shfl_xor_sync(0xffffffffu, v, off);
            int   oi = __shfl_xor_sync(0xffffffffu, idx, off);
            if (ov > v || (ov == v && oi < idx)) { v = ov; idx = oi; }
        }
        sc[h] = v; cd[h] = idx;
    }
    if (lane == 0) {
        int h1 = 0;
#pragma unroll
        for (int h = 1; h < Hh; h++) if (sc[h] > sc[h1]) h1 = h;
        int h2 = -1;
#pragma unroll
        for (int h = 0; h < Hh; h++) {
            if (h == h1) continue;
            if (h2 < 0 || sc[h] > sc[h2]) h2 = h;
        }
        int e0 = cd[h1], e1 = cd[h2];
        int p0 = atomicAdd(&g_count[e0], 1);
        if (p0 < CAP) g_toklist[e0 * CAP + p0] = t * 2;
        int p1 = atomicAdd(&g_count[e1], 1);
        if (p1 < CAP) g_toklist[e1 * CAP + p1] = t * 2 + 1;
    }
}

// ================================================================ FFN kernel A
// Dynamic-smem, KCH=32, CTA 128x128, 8 warps (64x32 warp tile), fragment
// double-buffered: STS/LDG/ldsm-set1 drain under the mma stream.
template <bool F1>
__global__ __launch_bounds__(256, 1)
void moe_mma_d(const float* __restrict__ x, const float* __restrict__ W) {
    const int KTOT = F1 ? Dm : Fm;
    const int NTOT = F1 ? Fm : Dm;
    const int NKC  = KTOT / DKCH;   // 16 / 64

    const int e = blockIdx.z;
    const int n_e = min(g_count[e], CAP);
    const int m0 = blockIdx.y * 128;
    if (m0 >= n_e) return;
    const int bn = blockIdx.x * 128;

    extern __shared__ char dsm[];
    __shared__ int stok[128];
    const uint32_t sbase = (uint32_t)__cvta_generic_to_shared(dsm);

    const int tid  = threadIdx.x;
    const int lane = tid & 31;
    const int wid  = tid >> 5;
    const int wm   = wid & 1;       // 2 m-warps (64 rows each)
    const int wn   = wid >> 1;      // 4 n-warps (32 cols each)
    const int g    = lane >> 2;
    const int t2   = (lane & 3) * 2;

    if (tid < 128) {
        int r = m0 + tid;
        stok[tid] = (r < n_e) ? g_toklist[e * CAP + r] : 0;
    }
    __syncthreads();

    // producers: A row arow, 16 k-floats (half ahalf); B k-row kr, 16 n-floats
    const int arow  = tid >> 1;
    const int ahalf = tid & 1;
    const int aslot = stok[arow];
    const float* arp = (F1 ? (x + (size_t)(aslot >> 1) * Dm)
                           : (g_hbuf + (size_t)aslot * Fm)) + ahalf * 16;
    const int kr = tid >> 3;            // 0..31
    const int nq = (tid & 7) * 16;      // 0..112
    const float* wrp = W + (size_t)e * KTOT * NTOT + (size_t)kr * NTOT + bn + nq;

    float4 ar[4], wr[4];
    auto ldg_chunk = [&](int kc) {
        const float4* ap = (const float4*)(arp + kc * DKCH);
#pragma unroll
        for (int j = 0; j < 4; j++) ar[j] = ap[j];
        const float4* wp = (const float4*)(wrp + (size_t)kc * DKCH * NTOT);
#pragma unroll
        for (int j = 0; j < 4; j++) wr[j] = wp[j];
    };
    auto sts_chunk = [&](int b) {
        char* pah = dsm + OFF_AH(b) + (arow * DSPAD + ahalf * 16) * 2;
        char* pal = dsm + OFF_AL(b) + (arow * DSPAD + ahalf * 16) * 2;
#pragma unroll
        for (int j = 0; j < 4; j++) {
            uint2 h, l;
            split4h(ar[j], h, l);
            *(uint2*)(pah + j * 8) = h;
            *(uint2*)(pal + j * 8) = l;
        }
        char* pb = dsm + OFF_BH(b) + (kr * DBNP + nq) * 2;
#pragma unroll
        for (int j = 0; j < 4; j++)
            *(uint2*)(pb + j * 8) = hi4h(wr[j]);
    };

    // consumer ldmatrix lane addressing (R10-proven mappings)
    const int a_r  = lane & 15;
    const int a_c  = (lane >> 4) * 8;
    const int b_m  = lane >> 3;
    const int b_kr = (b_m & 1) * 8 + (lane & 7);
    const int b_n0 = wn * 32 + (b_m >> 1) * 8;

    float acc[4][4][4];
#pragma unroll
    for (int mi = 0; mi < 4; mi++)
#pragma unroll
        for (int ni = 0; ni < 4; ni++)
#pragma unroll
            for (int q = 0; q < 4; q++) acc[mi][ni][q] = 0.0f;

    uint32_t ah0[4][4], al0[4][4], bh0[4][2];
    uint32_t ah1[4][4], al1[4][4], bh1[4][2];

    auto load_frags = [&](int cur, int kb, uint32_t (*ah)[4], uint32_t (*al)[4],
                          uint32_t (*bh)[2]) {
        uint32_t bah = sbase + OFF_AH(cur);
        uint32_t bal = sbase + OFF_AL(cur);
        uint32_t bbh = sbase + OFF_BH(cur);
#pragma unroll
        for (int mi = 0; mi < 4; mi++) {
            uint32_t off = ((wm * 64 + mi * 16 + a_r) * DSPAD + kb + a_c) * 2;
            ldsm_x4(ah[mi][0], ah[mi][1], ah[mi][2], ah[mi][3], bah + off);
            ldsm_x4(al[mi][0], al[mi][1], al[mi][2], al[mi][3], bal + off);
        }
#pragma unroll
        for (int np = 0; np < 2; np++) {
            uint32_t off = ((kb + b_kr) * DBNP + b_n0 + np * 16) * 2;
            ldsm_x4_t(bh[np * 2][0], bh[np * 2][1], bh[np * 2 + 1][0], bh[np * 2 + 1][1],
                      bbh + off);
        }
    };
    auto mma_step = [&](uint32_t (*ah)[4], uint32_t (*al)[4], uint32_t (*bh)[2]) {
#pragma unroll
        for (int mi = 0; mi < 4; mi++)
#pragma unroll
            for (int ni = 0; ni < 4; ni++) {
                float* d = acc[mi][ni];
                mma_f16(d[0], d[1], d[2], d[3],
                        ah[mi][0], ah[mi][1], ah[mi][2], ah[mi][3],
                        bh[ni][0], bh[ni][1]);
                mma_f16(d[0], d[1], d[2], d[3],
                        al[mi][0], al[mi][1], al[mi][2], al[mi][3],
                        bh[ni][0], bh[ni][1]);
            }
    };

    // prologue: chunk0 -> buf0; chunk1 into regs
    ldg_chunk(0);
    sts_chunk(0);
    ldg_chunk(1);

    for (int kc = 0; kc < NKC; kc++) {
        const int cur = kc & 1;
        __syncthreads();                       // buffer 'cur' ready
        load_frags(cur, 0, ah0, al0, bh0);     // exposed ldsm (set 0)
        if (kc + 1 < NKC) sts_chunk(1 - cur);  // drains under mma set 0
        if (kc + 2 < NKC) ldg_chunk(kc + 2);
        mma_step(ah0, al0, bh0);
        load_frags(cur, 16, ah1, al1, bh1);    // overlaps mma set 0 retire
        mma_step(ah1, al1, bh1);
    }

    // epilogue (R10-proven layout)
#pragma unroll
    for (int mi = 0; mi < 4; mi++) {
#pragma unroll
        for (int half = 0; half < 2; half++) {
            int lr = wm * 64 + mi * 16 + g + half * 8;
            if (m0 + lr >= n_e) continue;
            int slot = stok[lr];
            float* orow = F1 ? (g_hbuf + (size_t)slot * Fm)
                             : (g_ybuf + (size_t)slot * Dm);
#pragma unroll
            for (int ni = 0; ni < 4; ni++) {
                int col = bn + wn * 32 + ni * 8 + t2;
                float v0 = acc[mi][ni][half * 2 + 0];
                float v1 = acc[mi][ni][half * 2 + 1];
                if (F1) { v0 = gelu_exact(v0); v1 = gelu_exact(v1); }
                *(float2*)(orow + col) = make_float2(v0, v1);
            }
        }
    }
}

// ================================================================ FFN kernel B
// Static-smem fallback: EXACT R12 kernel (proven 818us).
template <bool F1>
__global__ __launch_bounds__(256, 1)
void moe_mma_s(const float* __restrict__ x, const float* __restrict__ W) {
    const int KTOT = F1 ? Dm : Fm;
    const int NTOT = F1 ? Fm : Dm;
    const int NKC  = KTOT / KCH;

    const int e = blockIdx.z;
    const int n_e = min(g_count[e], CAP);
    const int m0 = blockIdx.y * 128;
    if (m0 >= n_e) return;
    const int bn = blockIdx.x * 256;

    __shared__ __align__(16) __half sAh[2][128 * SPAD];
    __shared__ __align__(16) __half sAl[2][128 * SPAD];
    __shared__ __align__(16) __half sBh[2][KCH * BNP2];
    __shared__ int stok[128];

    const int tid  = threadIdx.x;
    const int lane = tid & 31;
    const int wid  = tid >> 5;
    const int wm   = wid & 1;
    const int wn   = wid >> 1;
    const int g    = lane >> 2;
    const int t2   = (lane & 3) * 2;

    if (tid < 128) {
        int r = m0 + tid;
        stok[tid] = (r < n_e) ? g_toklist[e * CAP + r] : 0;
    }
    __syncthreads();

    const int arow  = tid >> 1;
    const int ahalf = tid & 1;
    const int aslot = stok[arow];
    const float* arp = (F1 ? (x + (size_t)(aslot >> 1) * Dm)
                           : (g_hbuf + (size_t)aslot * Fm)) + ahalf * 8;
    const int kr = tid >> 4;
    const int nq = (tid & 15) * 16;
    const float* wrp = W + (size_t)e * KTOT * NTOT + (size_t)kr * NTOT + bn + nq;

    float4 areg0[2], areg1[2], wreg0[4], wreg1[4];
    auto ldg_chunk = [&](int kc, float4* ar, float4* wr) {
        const float4* ap = (const float4*)(arp + kc * KCH);
        ar[0] = ap[0];
        ar[1] = ap[1];
        const float4* wk = (const float4*)(wrp + (size_t)kc * KCH * NTOT);
#pragma unroll
        for (int j = 0; j < 4; j++) wr[j] = wk[j];
    };
    auto sts_chunk = [&](int s, const float4* ar, const float4* wr) {
        uint2 h0, l0, h1, l1;
        split4h(ar[0], h0, l0);
        split4h(ar[1], h1, l1);
        int acol = ahalf * 8;
        char* pah = (char*)sAh[s] + (arow * SPAD + acol) * 2;
        char* pal = (char*)sAl[s] + (arow * SPAD + acol) * 2;
        *(uint2*)(pah)     = h0;
        *(uint2*)(pah + 8) = h1;
        *(uint2*)(pal)     = l0;
        *(uint2*)(pal + 8) = l1;
        uint2 b0 = hi4h(wr[0]), b1 = hi4h(wr[1]), b2 = hi4h(wr[2]), b3 = hi4h(wr[3]);
        char* pb = (char*)sBh[s] + (kr * BNP2 + nq) * 2;
        *(uint4*)(pb)      = make_uint4(b0.x, b0.y, b1.x, b1.y);
        *(uint4*)(pb + 16) = make_uint4(b2.x, b2.y, b3.x, b3.y);
    };

    const int a_r = lane & 15;
    const int a_c = (lane >> 4) * 8;
    const int b_m  = lane >> 3;
    const int b_kr = (b_m & 1) * 8 + (lane & 7);
    const int b_n0 = wn * 64 + (b_m >> 1) * 8;

    float acc[4][8][4];
#pragma unroll
    for (int mi = 0; mi < 4; mi++)
#pragma unroll
        for (int ni = 0; ni < 8; ni++)
#pragma unroll
            for (int q = 0; q < 4; q++) acc[mi][ni][q] = 0.0f;

    auto compute = [&](int cur) {
        uint32_t ah[4][4], al[4][4], bh[8][2];
        uint32_t baseAh = (uint32_t)__cvta_generic_to_shared(sAh[cur]);
        uint32_t baseAl = (uint32_t)__cvta_generic_to_shared(sAl[cur]);
        uint32_t baseBh = (uint32_t)__cvta_generic_to_shared(sBh[cur]);
#pragma unroll
        for (int mi = 0; mi < 4; mi++) {
            uint32_t off = ((wm * 64 + mi * 16 + a_r) * SPAD + a_c) * 2;
            ldsm_x4(ah[mi][0], ah[mi][1], ah[mi][2], ah[mi][3], baseAh + off);
            ldsm_x4(al[mi][0], al[mi][1], al[mi][2], al[mi][3], baseAl + off);
        }
#pragma unroll
        for (int np = 0; np < 4; np++) {
            uint32_t off = (b_kr * BNP2 + b_n0 + np * 16) * 2;
            ldsm_x4_t(bh[np * 2][0], bh[np * 2][1], bh[np * 2 + 1][0], bh[np * 2 + 1][1],
                      baseBh + off);
        }
#pragma unroll
        for (int mi = 0; mi < 4; mi++)
#pragma unroll
            for (int ni = 0; ni < 8; ni++) {
                float* d = acc[mi][ni];
                mma_f16(d[0], d[1], d[2], d[3],
                        ah[mi][0], ah[mi][1], ah[mi][2], ah[mi][3],
                        bh[ni][0], bh[ni][1]);
                mma_f16(d[0], d[1], d[2], d[3],
                        al[mi][0], al[mi][1], al[mi][2], al[mi][3],
                        bh[ni][0], bh[ni][1]);
            }
    };

    ldg_chunk(0, areg0, wreg0);
    ldg_chunk(1, areg1, wreg1);

    for (int kc = 0; kc < NKC; kc += 2) {
        sts_chunk(0, areg0, wreg0);
        if (kc + 2 < NKC) ldg_chunk(kc + 2, areg0, wreg0);
        __syncthreads();
        compute(0);
        sts_chunk(1, areg1, wreg1);
        if (kc + 3 < NKC) ldg_chunk(kc + 3, areg1, wreg1);
        __syncthreads();
        compute(1);
    }

#pragma unroll
    for (int mi = 0; mi < 4; mi++) {
#pragma unroll
        for (int half = 0; half < 2; half++) {
            int lr = wm * 64 + mi * 16 + g + half * 8;
            if (m0 + lr >= n_e) continue;
            int slot = stok[lr];
            float* orow = F1 ? (g_hbuf + (size_t)slot * Fm)
                             : (g_ybuf + (size_t)slot * Dm);
#pragma unroll
            for (int ni = 0; ni < 8; ni++) {
                int col = bn + wn * 64 + ni * 8 + t2;
                float v0 = acc[mi][ni][half * 2 + 0];
                float v1 = acc[mi][ni][half * 2 + 1];
                if (F1) { v0 = gelu_exact(v0); v1 = gelu_exact(v1); }
                *(float2*)(orow + col) = make_float2(v0, v1);
            }
        }
    }
}

// ---------------------------------------------------------------- combine
__global__ void combine_kernel(float* __restrict__ out) {
    int i = blockIdx.x * 256 + threadIdx.x;     // float4 index
    if (i >= T_TOK * Dm / 4) return;
    int t = i >> 7;
    int c = i & 127;
    const float4* y = (const float4*)g_ybuf;
    float4 a = y[(size_t)(2 * t) * 128 + c];
    float4 b = y[(size_t)(2 * t + 1) * 128 + c];
    ((float4*)out)[i] = make_float4(0.5f * (a.x + b.x), 0.5f * (a.y + b.y),
                                    0.5f * (a.z + b.z), 0.5f * (a.w + b.w));
}

// ---------------------------------------------------------------- launcher
extern "C" void kernel_launch(void* const* d_in, const int* in_sizes, int n_in,
                              void* d_out, int out_size) {
    const float* x  = (const float*)d_in[0];
    const float* hp = (const float*)d_in[1];
    const float* W1 = (const float*)d_in[2];
    const float* W2 = (const float*)d_in[3];
    float* out = (float*)d_out;

    zc_kernel<<<1, 64>>>();
    route_gemm<<<dim3(NC / BN, T_TOK / BM), 256>>>(x, hp);
    route_top2_dispatch<<<(T_TOK * 32) / 256, 256>>>();

    cudaError_t ea = cudaFuncSetAttribute(moe_mma_d<true>,
                                          cudaFuncAttributeMaxDynamicSharedMemorySize, DSMEM);
    cudaError_t eb = cudaFuncSetAttribute(moe_mma_d<false>,
                                          cudaFuncAttributeMaxDynamicSharedMemorySize, DSMEM);
    if (ea == cudaSuccess && eb == cudaSuccess) {
        moe_mma_d<true><<<dim3(Fm / 128, CAP / 128, Em), 256, DSMEM>>>(x, W1);
        moe_mma_d<false><<<dim3(Dm / 128, CAP / 128, Em), 256, DSMEM>>>(nullptr, W2);
    } else {
        (void)cudaGetLastError();   // clear, fall back to proven static kernel
        moe_mma_s<true><<<dim3(Fm / 256, CAP / 128, Em), 256>>>(x, W1);
        moe_mma_s<false><<<dim3(Dm / 256, CAP / 128, Em), 256>>>(nullptr, W2);
    }
    combine_kernel<<<(T_TOK * Dm / 4 + 255) / 256, 256>>>(out);
}

// round 15
// speedup vs baseline: 1.3736x; 1.3736x over previous
#include <cuda_runtime.h>
#include <cuda_fp16.h>
#include <math.h>
#include <stdint.h>

// ---------------------------------------------------------------- constants
#define T_TOK 8192
#define Dm    512
#define Fm    2048
#define Em    64
#define Hh    4
#define NC    256
#define CAP   1024
#define NSLOT (T_TOK * 2)

// routing fp32 GEMM tiling
#define BM 128
#define BN 128
#define BK 8

// mma FFN tiling: CTA 128m x 256n, 256 threads (2x4 warps, 64x64 warp tile),
// K-chunk 16, double-buffered smem, depth-2 register prefetch, plain fp16.
#define KCH   16
#define SPAD  24     // A smem row stride (fp16): 16 k + 8 pad
#define BNP2  264    // B smem row stride (fp16): 256 n + 8 pad

// ---------------------------------------------------------------- scratch
__device__ __align__(256) float g_logits[(size_t)T_TOK * NC];
__device__ __align__(256) int   g_count[Em];
__device__ __align__(256) int   g_toklist[Em * CAP];
__device__ __align__(256) float g_hbuf[(size_t)NSLOT * Fm];
__device__ __align__(256) float g_ybuf[(size_t)NSLOT * Dm];

// ---------------------------------------------------------------- helpers
__device__ __forceinline__ float gelu_exact(float v) {
    return 0.5f * v * (1.0f + erff(v * 0.7071067811865475f));
}
__device__ __forceinline__ uint32_t pack_h(__half a, __half b) {
    return (uint32_t)__half_as_ushort(a) | ((uint32_t)__half_as_ushort(b) << 16);
}
// fp16 round-nearest of 4 floats
__device__ __forceinline__ uint2 hi4h(float4 v) {
    return make_uint2(pack_h(__float2half_rn(v.x), __float2half_rn(v.y)),
                      pack_h(__float2half_rn(v.z), __float2half_rn(v.w)));
}
__device__ __forceinline__ void mma_f16(float& d0, float& d1, float& d2, float& d3,
                                        uint32_t a0, uint32_t a1, uint32_t a2, uint32_t a3,
                                        uint32_t b0, uint32_t b1) {
    asm volatile(
        "mma.sync.aligned.m16n8k16.row.col.f32.f16.f16.f32 "
        "{%0,%1,%2,%3},{%4,%5,%6,%7},{%8,%9},{%0,%1,%2,%3};"
        : "+f"(d0), "+f"(d1), "+f"(d2), "+f"(d3)
        : "r"(a0), "r"(a1), "r"(a2), "r"(a3), "r"(b0), "r"(b1));
}
__device__ __forceinline__ void ldsm_x4(uint32_t& r0, uint32_t& r1, uint32_t& r2, uint32_t& r3,
                                        uint32_t addr) {
    asm volatile("ldmatrix.sync.aligned.m8n8.x4.shared.b16 {%0,%1,%2,%3}, [%4];"
                 : "=r"(r0), "=r"(r1), "=r"(r2), "=r"(r3) : "r"(addr));
}
__device__ __forceinline__ void ldsm_x4_t(uint32_t& r0, uint32_t& r1, uint32_t& r2, uint32_t& r3,
                                          uint32_t addr) {
    asm volatile("ldmatrix.sync.aligned.m8n8.x4.trans.shared.b16 {%0,%1,%2,%3}, [%4];"
                 : "=r"(r0), "=r"(r1), "=r"(r2), "=r"(r3) : "r"(addr));
}

// ---------------------------------------------------------------- K0: misc
__global__ void zc_kernel() {
    if (threadIdx.x < Em) g_count[threadIdx.x] = 0;
}

// ---------------------------------------------------------------- routing (proven, fp32-exact)
__global__ __launch_bounds__(256, 2)
void route_gemm(const float* __restrict__ x, const float* __restrict__ hp) {
    __shared__ float As[BK][BM + 4];
    __shared__ float Bs[BK][BN];
    const int tid = threadIdx.x;
    const int bm = blockIdx.y * BM;
    const int bn = blockIdx.x * BN;
    const int arow = tid >> 1, akq = (tid & 1) << 2;
    const int bkr = tid >> 5, bnq = (tid & 31) << 2;
    const int tx = tid & 15, ty = tid >> 4;

    const int c = bn + bnq;
    const float* bsrc = hp + (c >> 6) * (Dm * Em) + bkr * Em + (c & 63);
    const float* asrc = x + (size_t)(bm + arow) * Dm + akq;

    float acc[8][8];
#pragma unroll
    for (int i = 0; i < 8; i++)
#pragma unroll
        for (int j = 0; j < 8; j++) acc[i][j] = 0.0f;

    for (int k0 = 0; k0 < Dm; k0 += BK) {
        float4 av = *(const float4*)(asrc + k0);
        float4 bv = *(const float4*)(bsrc + (size_t)k0 * Em);
        As[akq + 0][arow] = av.x;
        As[akq + 1][arow] = av.y;
        As[akq + 2][arow] = av.z;
        As[akq + 3][arow] = av.w;
        *(float4*)&Bs[bkr][bnq] = bv;
        __syncthreads();
        float ar[8], br[8];
#pragma unroll
        for (int k = 0; k < BK; k++) {
            *(float4*)&ar[0] = *(const float4*)&As[k][ty * 4];
            *(float4*)&ar[4] = *(const float4*)&As[k][64 + ty * 4];
            *(float4*)&br[0] = *(const float4*)&Bs[k][tx * 4];
            *(float4*)&br[4] = *(const float4*)&Bs[k][64 + tx * 4];
#pragma unroll
            for (int i = 0; i < 8; i++)
#pragma unroll
                for (int j = 0; j < 8; j++)
                    acc[i][j] = fmaf(ar[i], br[j], acc[i][j]);
        }
        __syncthreads();
    }
#pragma unroll
    for (int i = 0; i < 8; i++) {
        int m = bm + ((i < 4) ? (ty * 4 + i) : (64 + ty * 4 + i - 4));
        float* dst = g_logits + (size_t)m * NC + bn;
        *(float4*)(dst + tx * 4)      = make_float4(acc[i][0], acc[i][1], acc[i][2], acc[i][3]);
        *(float4*)(dst + 64 + tx * 4) = make_float4(acc[i][4], acc[i][5], acc[i][6], acc[i][7]);
    }
}

// fused top-2 routing + dispatch
__global__ void route_top2_dispatch() {
    int t = (blockIdx.x * blockDim.x + threadIdx.x) >> 5;
    int lane = threadIdx.x & 31;
    if (t >= T_TOK) return;
    const float* lg = g_logits + (size_t)t * NC;
    float sc[Hh]; int cd[Hh];
#pragma unroll
    for (int h = 0; h < Hh; h++) {
        float v0 = lg[h * 64 + lane];
        float v1 = lg[h * 64 + 32 + lane];
        float v = v0; int idx = lane;
        if (v1 > v) { v = v1; idx = lane + 32; }
#pragma unroll
        for (int off = 16; off > 0; off >>= 1) {
            float ov = __shfl_xor_sync(0xffffffffu, v, off);
            int   oi = __shfl_xor_sync(0xffffffffu, idx, off);
            if (ov > v || (ov == v && oi < idx)) { v = ov; idx = oi; }
        }
        sc[h] = v; cd[h] = idx;
    }
    if (lane == 0) {
        int h1 = 0;
#pragma unroll
        for (int h = 1; h < Hh; h++) if (sc[h] > sc[h1]) h1 = h;
        int h2 = -1;
#pragma unroll
        for (int h = 0; h < Hh; h++) {
            if (h == h1) continue;
            if (h2 < 0 || sc[h] > sc[h2]) h2 = h;
        }
        int e0 = cd[h1], e1 = cd[h2];
        int p0 = atomicAdd(&g_count[e0], 1);
        if (p0 < CAP) g_toklist[e0 * CAP + p0] = t * 2;
        int p1 = atomicAdd(&g_count[e1], 1);
        if (p1 < CAP) g_toklist[e1 * CAP + p1] = t * 2 + 1;
    }
}

// ------------------------------------------------- mma.sync grouped GEMM
// Plain fp16 (A = hi, B = hi). CTA 128m x 256n, 8 warps (warp tile 64x64),
// KCH=16, double-buffered static smem, depth-2 reg prefetch. Structure is
// the R12-proven kernel minus the A-lo term.
template <bool F1>
__global__ __launch_bounds__(256, 1)
void moe_mma(const float* __restrict__ x, const float* __restrict__ W) {
    const int KTOT = F1 ? Dm : Fm;
    const int NTOT = F1 ? Fm : Dm;
    const int NKC  = KTOT / KCH;   // 32 / 128, even

    const int e = blockIdx.z;
    const int n_e = min(g_count[e], CAP);
    const int m0 = blockIdx.y * 128;
    if (m0 >= n_e) return;
    const int bn = blockIdx.x * 256;

    __shared__ __align__(16) __half sAh[2][128 * SPAD];
    __shared__ __align__(16) __half sBh[2][KCH * BNP2];
    __shared__ int stok[128];

    const int tid  = threadIdx.x;
    const int lane = tid & 31;
    const int wid  = tid >> 5;
    const int wm   = wid & 1;       // warp M index (2)
    const int wn   = wid >> 1;      // warp N index (4)
    const int g    = lane >> 2;
    const int t2   = (lane & 3) * 2;

    if (tid < 128) {
        int r = m0 + tid;
        stok[tid] = (r < n_e) ? g_toklist[e * CAP + r] : 0;
    }
    __syncthreads();

    // producers: A row arow (0..127) x 8 k-floats; B k-row kr x 16 n-floats
    const int arow  = tid >> 1;
    const int ahalf = tid & 1;
    const int aslot = stok[arow];
    const float* arp = (F1 ? (x + (size_t)(aslot >> 1) * Dm)
                           : (g_hbuf + (size_t)aslot * Fm)) + ahalf * 8;
    const int kr = tid >> 4;
    const int nq = (tid & 15) * 16;
    const float* wrp = W + (size_t)e * KTOT * NTOT + (size_t)kr * NTOT + bn + nq;

    float4 areg0[2], areg1[2], wreg0[4], wreg1[4];
    auto ldg_chunk = [&](int kc, float4* ar, float4* wr) {
        const float4* ap = (const float4*)(arp + kc * KCH);
        ar[0] = ap[0];
        ar[1] = ap[1];
        const float4* wk = (const float4*)(wrp + (size_t)kc * KCH * NTOT);
#pragma unroll
        for (int j = 0; j < 4; j++) wr[j] = wk[j];
    };
    auto sts_chunk = [&](int s, const float4* ar, const float4* wr) {
        uint2 a0 = hi4h(ar[0]), a1 = hi4h(ar[1]);
        int acol = ahalf * 8;
        char* pah = (char*)sAh[s] + (arow * SPAD + acol) * 2;
        *(uint2*)(pah)     = a0;
        *(uint2*)(pah + 8) = a1;
        uint2 b0 = hi4h(wr[0]), b1 = hi4h(wr[1]), b2 = hi4h(wr[2]), b3 = hi4h(wr[3]);
        char* pb = (char*)sBh[s] + (kr * BNP2 + nq) * 2;
        *(uint4*)(pb)      = make_uint4(b0.x, b0.y, b1.x, b1.y);
        *(uint4*)(pb + 16) = make_uint4(b2.x, b2.y, b3.x, b3.y);
    };

    // consumer ldmatrix lane addressing (R9-R12 proven mappings)
    const int a_r = lane & 15;
    const int a_c = (lane >> 4) * 8;
    const int b_m  = lane >> 3;
    const int b_kr = (b_m & 1) * 8 + (lane & 7);
    const int b_n0 = wn * 64 + (b_m >> 1) * 8;

    float acc[4][8][4];
#pragma unroll
    for (int mi = 0; mi < 4; mi++)
#pragma unroll
        for (int ni = 0; ni < 8; ni++)
#pragma unroll
            for (int q = 0; q < 4; q++) acc[mi][ni][q] = 0.0f;

    auto compute = [&](int cur) {
        uint32_t ah[4][4], bh[8][2];
        uint32_t baseAh = (uint32_t)__cvta_generic_to_shared(sAh[cur]);
        uint32_t baseBh = (uint32_t)__cvta_generic_to_shared(sBh[cur]);
#pragma unroll
        for (int mi = 0; mi < 4; mi++) {
            uint32_t off = ((wm * 64 + mi * 16 + a_r) * SPAD + a_c) * 2;
            ldsm_x4(ah[mi][0], ah[mi][1], ah[mi][2], ah[mi][3], baseAh + off);
        }
#pragma unroll
        for (int np = 0; np < 4; np++) {
            uint32_t off = (b_kr * BNP2 + b_n0 + np * 16) * 2;
            ldsm_x4_t(bh[np * 2][0], bh[np * 2][1], bh[np * 2 + 1][0], bh[np * 2 + 1][1],
                      baseBh + off);
        }
#pragma unroll
        for (int mi = 0; mi < 4; mi++)
#pragma unroll
            for (int ni = 0; ni < 8; ni++) {
                float* d = acc[mi][ni];
                mma_f16(d[0], d[1], d[2], d[3],
                        ah[mi][0], ah[mi][1], ah[mi][2], ah[mi][3],
                        bh[ni][0], bh[ni][1]);
            }
    };

    // depth-2 pipeline
    ldg_chunk(0, areg0, wreg0);
    ldg_chunk(1, areg1, wreg1);

    for (int kc = 0; kc < NKC; kc += 2) {
        sts_chunk(0, areg0, wreg0);
        if (kc + 2 < NKC) ldg_chunk(kc + 2, areg0, wreg0);
        __syncthreads();
        compute(0);
        sts_chunk(1, areg1, wreg1);
        if (kc + 3 < NKC) ldg_chunk(kc + 3, areg1, wreg1);
        __syncthreads();
        compute(1);
    }

    // epilogue (proven layout)
#pragma unroll
    for (int mi = 0; mi < 4; mi++) {
#pragma unroll
        for (int half = 0; half < 2; half++) {
            int lr = wm * 64 + mi * 16 + g + half * 8;
            if (m0 + lr >= n_e) continue;
            int slot = stok[lr];
            float* orow = F1 ? (g_hbuf + (size_t)slot * Fm)
                             : (g_ybuf + (size_t)slot * Dm);
#pragma unroll
            for (int ni = 0; ni < 8; ni++) {
                int col = bn + wn * 64 + ni * 8 + t2;
                float v0 = acc[mi][ni][half * 2 + 0];
                float v1 = acc[mi][ni][half * 2 + 1];
                if (F1) { v0 = gelu_exact(v0); v1 = gelu_exact(v1); }
                *(float2*)(orow + col) = make_float2(v0, v1);
            }
        }
    }
}

// ---------------------------------------------------------------- combine
__global__ void combine_kernel(float* __restrict__ out) {
    int i = blockIdx.x * 256 + threadIdx.x;     // float4 index
    if (i >= T_TOK * Dm / 4) return;
    int t = i >> 7;
    int c = i & 127;
    const float4* y = (const float4*)g_ybuf;
    float4 a = y[(size_t)(2 * t) * 128 + c];
    float4 b = y[(size_t)(2 * t + 1) * 128 + c];
    ((float4*)out)[i] = make_float4(0.5f * (a.x + b.x), 0.5f * (a.y + b.y),
                                    0.5f * (a.z + b.z), 0.5f * (a.w + b.w));
}

// ---------------------------------------------------------------- launcher
extern "C" void kernel_launch(void* const* d_in, const int* in_sizes, int n_in,
                              void* d_out, int out_size) {
    const float* x  = (const float*)d_in[0];
    const float* hp = (const float*)d_in[1];
    const float* W1 = (const float*)d_in[2];
    const float* W2 = (const float*)d_in[3];
    float* out = (float*)d_out;

    zc_kernel<<<1, 64>>>();
    route_gemm<<<dim3(NC / BN, T_TOK / BM), 256>>>(x, hp);
    route_top2_dispatch<<<(T_TOK * 32) / 256, 256>>>();
    moe_mma<true><<<dim3(Fm / 256, CAP / 128, Em), 256>>>(x, W1);
    moe_mma<false><<<dim3(Dm / 256, CAP / 128, Em), 256>>>(nullptr, W2);
    combine_kernel<<<(T_TOK * Dm / 4 + 255) / 256, 256>>>(out);
}